// round 1
// baseline (speedup 1.0000x reference)
#include <cuda_runtime.h>
#include <cstdint>

// Flow_68015102099543: out[b,o,h,w] = bias[o] + sum_{i,c} comb[o, i*16+c] * x[b,c,h+dy_i,w+dx_i]
// == 3x3 cross-correlation, padding=1. B=4, C=16, O=16, H=450, W=480, fp32.

#define C_IN 16
#define O_OUT 16
#define HH 450
#define WW 480

typedef unsigned long long u64;

__device__ __forceinline__ u64 pk2(float lo, float hi) {
    u64 r;
    asm("mov.b64 %0, {%1, %2};" : "=l"(r) : "f"(lo), "f"(hi));
    return r;
}

__device__ __forceinline__ void fma2(u64& d, u64 a, u64 b) {
    // packed f32x2 fused multiply-add: d = a*b + d (lanewise, 2x fp32)
    asm("fma.rn.f32x2 %0, %1, %2, %0;" : "+l"(d) : "l"(a), "l"(b));
}

__global__ void __launch_bounds__(256, 2) flow_conv3x3_kernel(
    const float* __restrict__ x,      // [4,16,450,480]
    const float* __restrict__ comb,   // [16,144]  (o, i*16+c)
    const float* __restrict__ bias,   // [16]
    float* __restrict__ out)          // [4,16,450,480]
{
    // Weights duplicated as (w,w) pairs in smem: ws[(i*16+c)*16 + o]
    __shared__ u64 ws[9 * C_IN * O_OUT];  // 2304 * 8B = 18 KB

    const int tid = threadIdx.x;
    for (int idx = tid; idx < 9 * C_IN * O_OUT; idx += 256) {
        int ic = idx >> 4;       // i*16 + c
        int o  = idx & 15;
        float v = comb[o * (9 * C_IN) + ic];
        ws[idx] = pk2(v, v);
    }
    __syncthreads();

    // thread mapping: o_half (2) x wc (8) x lh (16)
    const int o_half = tid & 1;
    const int wc     = (tid >> 1) & 7;
    const int lh     = tid >> 4;

    const int b     = blockIdx.z;
    const int h     = blockIdx.y * 16 + lh;
    const int wbase = blockIdx.x * 64 + wc * 8;
    if (h >= HH || wbase >= WW) return;

    const int obase = o_half * 8;

    // 8 output channels x 4 pixel-pairs, packed f32x2 accumulators, init = bias
    u64 acc[8][4];
#pragma unroll
    for (int oo = 0; oo < 8; oo++) {
        float bv = __ldg(bias + obase + oo);
        u64 bp = pk2(bv, bv);
        acc[oo][0] = bp; acc[oo][1] = bp; acc[oo][2] = bp; acc[oo][3] = bp;
    }

    const bool left_ok  = (wbase > 0);
    const bool right_ok = (wbase + 8 < WW);

    const float* xb = x + (size_t)b * C_IN * HH * WW;

#pragma unroll 1
    for (int c = 0; c < C_IN; c++) {
        const float* xc = xb + (size_t)c * (HH * WW);
#pragma unroll
        for (int dy = 0; dy < 3; dy++) {
            const int r = h - 1 + dy;
            // Load 10-wide input strip xv[0..9] = x[c][r][wbase-1 .. wbase+8]
            float2 a0 = {0.f, 0.f}, a1 = {0.f, 0.f}, a2 = {0.f, 0.f}, a3 = {0.f, 0.f};
            float x0 = 0.f, x9 = 0.f;
            if ((unsigned)r < (unsigned)HH) {
                const float* rp = xc + r * WW + wbase;   // 8-float aligned
                a0 = __ldg((const float2*)(rp + 0));
                a1 = __ldg((const float2*)(rp + 2));
                a2 = __ldg((const float2*)(rp + 4));
                a3 = __ldg((const float2*)(rp + 6));
                if (left_ok)  x0 = __ldg(rp - 1);
                if (right_ok) x9 = __ldg(rp + 8);
            }
            // kx=1 pairs (aligned)
            const u64 P0 = pk2(a0.x, a0.y);
            const u64 P1 = pk2(a1.x, a1.y);
            const u64 P2 = pk2(a2.x, a2.y);
            const u64 P3 = pk2(a3.x, a3.y);
            // shifted pairs: L[k] = (xv[2k], xv[2k+1]);  kx=0 -> L0..L3, kx=2 -> L1..L4
            const u64 L0 = pk2(x0,   a0.x);
            const u64 L1 = pk2(a0.y, a1.x);
            const u64 L2 = pk2(a1.y, a2.x);
            const u64 L3 = pk2(a2.y, a3.x);
            const u64 L4 = pk2(a3.y, x9);

            // weight base for (dy, kx=0, c): ws[((dy*3+kx)*16 + c)*16 + o]
            const u64* wrow = ws + (dy * 3 * C_IN + c) * O_OUT + obase;

#pragma unroll
            for (int kx = 0; kx < 3; kx++) {
                u64 p0, p1, p2, p3;
                if (kx == 0)      { p0 = L0; p1 = L1; p2 = L2; p3 = L3; }
                else if (kx == 1) { p0 = P0; p1 = P1; p2 = P2; p3 = P3; }
                else              { p0 = L1; p1 = L2; p2 = L3; p3 = L4; }
                const u64* wp = wrow + kx * (C_IN * O_OUT);
#pragma unroll
                for (int oo = 0; oo < 8; oo++) {
                    const u64 w2 = wp[oo];   // LDS.64 broadcast (2 addrs/warp)
                    fma2(acc[oo][0], w2, p0);
                    fma2(acc[oo][1], w2, p1);
                    fma2(acc[oo][2], w2, p2);
                    fma2(acc[oo][3], w2, p3);
                }
            }
        }
    }

    // Store: 8 channels x 8 pixels; wbase is 8-aligned -> 8B-aligned u64 stores
    float* op = out + (((size_t)b * O_OUT + obase) * HH + h) * WW + wbase;
#pragma unroll
    for (int oo = 0; oo < 8; oo++) {
        u64* q = (u64*)op;
        q[0] = acc[oo][0];
        q[1] = acc[oo][1];
        q[2] = acc[oo][2];
        q[3] = acc[oo][3];
        op += (size_t)HH * WW;
    }
}

extern "C" void kernel_launch(void* const* d_in, const int* in_sizes, int n_in,
                              void* d_out, int out_size) {
    const float* x    = (const float*)d_in[0];   // 4*16*450*480
    const float* comb = (const float*)d_in[1];   // 16*144
    const float* bias = (const float*)d_in[2];   // 16
    float* out = (float*)d_out;

    dim3 grid((WW + 63) / 64, (HH + 15) / 16, 4);  // (8, 29, 4)
    flow_conv3x3_kernel<<<grid, 256>>>(x, comb, bias, out);
}

// round 2
// speedup vs baseline: 2.8407x; 2.8407x over previous
#include <cuda_runtime.h>
#include <cuda_bf16.h>
#include <cstdint>

// Flow_68015102099543 as implicit GEMM on tensor cores (bf16 hi/lo split, fp32 accum).
// out[b,o,h,w] = bias[o] + sum_{i,c} comb[o, i*16+c] * x[b,c,h+dy_i,w+dx_i]
// B=4, C=16, O=16, H=450, W=480. mma.sync m16n8k16: A = weights (16o x 16c per flow),
// B = patches (16c x 8pix), D = 16o x 8pix fp32.

#define HH 450
#define WW 480
#define CH 16
#define OC 16

#define HT 8           // output rows per block (one per warp)
#define WT 48          // output cols per block
#define WS 50          // staged width  (WT + 2)
#define HS 10          // staged height (HT + 2)
#define NGW 6          // 8-pixel groups per row

__device__ __forceinline__ uint32_t smem_u32(const void* p) {
    return (uint32_t)__cvta_generic_to_shared(p);
}

__device__ __forceinline__ void ldsm_x4(uint32_t& r0, uint32_t& r1, uint32_t& r2, uint32_t& r3,
                                        uint32_t a) {
    asm volatile("ldmatrix.sync.aligned.m8n8.x4.shared.b16 {%0,%1,%2,%3}, [%4];"
                 : "=r"(r0), "=r"(r1), "=r"(r2), "=r"(r3) : "r"(a));
}
__device__ __forceinline__ void ldsm_x2(uint32_t& r0, uint32_t& r1, uint32_t a) {
    asm volatile("ldmatrix.sync.aligned.m8n8.x2.shared.b16 {%0,%1}, [%2];"
                 : "=r"(r0), "=r"(r1) : "r"(a));
}

__device__ __forceinline__ void mma_bf16(float& d0, float& d1, float& d2, float& d3,
                                         uint32_t a0, uint32_t a1, uint32_t a2, uint32_t a3,
                                         uint32_t b0, uint32_t b1) {
    asm volatile("mma.sync.aligned.m16n8k16.row.col.f32.bf16.bf16.f32 "
                 "{%0,%1,%2,%3}, {%4,%5,%6,%7}, {%8,%9}, {%0,%1,%2,%3};"
                 : "+f"(d0), "+f"(d1), "+f"(d2), "+f"(d3)
                 : "r"(a0), "r"(a1), "r"(a2), "r"(a3), "r"(b0), "r"(b1));
}

__device__ __forceinline__ uint32_t pack_bf16x2(float lo_elem, float hi_elem) {
    __nv_bfloat162 v;
    v.x = __float2bfloat16(lo_elem);   // low 16 bits = first (even-c) element
    v.y = __float2bfloat16(hi_elem);
    return *(uint32_t*)&v;
}

__global__ void __launch_bounds__(256) flow_mma_kernel(
    const float* __restrict__ x,      // [4,16,450,480]
    const float* __restrict__ comb,   // [16,144]
    const float* __restrict__ bias,   // [16]
    float* __restrict__ out)          // [4,16,450,480]
{
    // x tile: [h_s][w_s][half] units of 16B (8 bf16 channels), half swizzled by (w_s>>2)&1
    __shared__ uint4 xhi4[HS * WS * 2];       // 16000 B
    __shared__ uint4 xlo4[HS * WS * 2];       // 16000 B
    // weights: [flow][o][half] units of 16B, half swizzled by (o>>2)&1
    __shared__ uint4 whi4[9 * OC * 2];        // 4608 B
    __shared__ uint4 wlo4[9 * OC * 2];        // 4608 B

    const int tid = threadIdx.x;
    const int b  = blockIdx.z;
    const int h0 = blockIdx.y * HT;
    const int w0 = blockIdx.x * WT;

    // ---- stage weights (split fp32 -> bf16 hi + bf16 lo) ----
    for (int idx = tid; idx < 9 * OC * CH; idx += 256) {
        int i = idx >> 8;          // flow 0..8
        int o = (idx >> 4) & 15;
        int c = idx & 15;
        float v = comb[o * 144 + i * 16 + c];
        __nv_bfloat16 hb = __float2bfloat16(v);
        __nv_bfloat16 lb = __float2bfloat16(v - __bfloat162float(hb));
        int half = c >> 3;
        int phys = (i * 16 + o) * 2 + (half ^ ((o >> 2) & 1));
        int eidx = phys * 8 + (c & 7);
        ((__nv_bfloat16*)whi4)[eidx] = hb;
        ((__nv_bfloat16*)wlo4)[eidx] = lb;
    }

    // ---- stage x tile: rows h0-1..h0+8, cols w0-1..w0+48, zero-padded ----
    for (int idx = tid; idx < HS * 2 * WS; idx += 256) {
        int w_s  = idx % WS;
        int t    = idx / WS;
        int half = t & 1;
        int h_s  = t >> 1;
        int gh = h0 - 1 + h_s;
        int gw = w0 - 1 + w_s;
        bool ok = ((unsigned)gh < (unsigned)HH) && ((unsigned)gw < (unsigned)WW);
        const float* xp = x + (((size_t)(b * CH + half * 8) * HH + gh) * WW + gw);
        float v[8];
#pragma unroll
        for (int cc = 0; cc < 8; cc++)
            v[cc] = ok ? __ldg(xp + (size_t)cc * (HH * WW)) : 0.0f;

        uint32_t uh[4], ul[4];
#pragma unroll
        for (int cc = 0; cc < 4; cc++) {
            float v0 = v[2 * cc], v1 = v[2 * cc + 1];
            __nv_bfloat16 h0b = __float2bfloat16(v0);
            __nv_bfloat16 h1b = __float2bfloat16(v1);
            float l0 = v0 - __bfloat162float(h0b);
            float l1 = v1 - __bfloat162float(h1b);
            __nv_bfloat162 hh; hh.x = h0b; hh.y = h1b;
            uh[cc] = *(uint32_t*)&hh;
            ul[cc] = pack_bf16x2(l0, l1);
        }
        int phys = (h_s * WS + w_s) * 2 + (half ^ ((w_s >> 2) & 1));
        xhi4[phys] = make_uint4(uh[0], uh[1], uh[2], uh[3]);
        xlo4[phys] = make_uint4(ul[0], ul[1], ul[2], ul[3]);
    }
    __syncthreads();

    const int warp = tid >> 5;
    const int lane = tid & 31;
    const int h = h0 + warp;
    if (h >= HH) return;   // whole-warp exit; no further barriers

    // D accumulators: d[g][0..1] = (o = lane>>2, pix = (lane&3)*2 + {0,1})
    //                 d[g][2..3] = (o+8, same pixels); init with bias.
    const int og = lane >> 2;
    const float b0v = __ldg(bias + og);
    const float b8v = __ldg(bias + 8 + og);
    float d[NGW][4];
#pragma unroll
    for (int g = 0; g < NGW; g++) { d[g][0] = b0v; d[g][1] = b0v; d[g][2] = b8v; d[g][3] = b8v; }

    const uint32_t whibase = smem_u32(whi4);
    const uint32_t wlobase = smem_u32(wlo4);
    const uint32_t xhibase = smem_u32(xhi4);
    const uint32_t xlobase = smem_u32(xlo4);

    // A fragment lane address (weights): 4 8x8 matrices in a0..a3 order
    const int o_l   = ((lane >> 3) & 1) * 8 + (lane & 7);
    const int ahalf = (lane >> 4) & 1;
    const uint32_t aoff = (uint32_t)((o_l * 2 + (ahalf ^ ((o_l >> 2) & 1))) * 16);

    // B fragment lane params: 2 8x8 matrices (pixels x c-halves)
    const int bp    = lane & 7;
    const int bhalf = (lane >> 3) & 1;

#pragma unroll
    for (int i = 0; i < 9; i++) {
        const int dy = i / 3, dx = i % 3;
        uint32_t ah0, ah1, ah2, ah3, al0, al1, al2, al3;
        ldsm_x4(ah0, ah1, ah2, ah3, whibase + (uint32_t)i * 512u + aoff);
        ldsm_x4(al0, al1, al2, al3, wlobase + (uint32_t)i * 512u + aoff);
        const int hrow = warp + dy;
#pragma unroll
        for (int g = 0; g < NGW; g++) {
            int w_s = dx + g * 8 + bp;
            uint32_t boff = (uint32_t)(((hrow * WS + w_s) * 2 + (bhalf ^ ((w_s >> 2) & 1))) * 16);
            uint32_t bh0, bh1, bl0, bl1;
            ldsm_x2(bh0, bh1, xhibase + boff);
            ldsm_x2(bl0, bl1, xlobase + boff);
            mma_bf16(d[g][0], d[g][1], d[g][2], d[g][3], ah0, ah1, ah2, ah3, bh0, bh1);
            mma_bf16(d[g][0], d[g][1], d[g][2], d[g][3], ah0, ah1, ah2, ah3, bl0, bl1);
            mma_bf16(d[g][0], d[g][1], d[g][2], d[g][3], al0, al1, al2, al3, bh0, bh1);
        }
    }

    // ---- store: 2 consecutive pixels per STG.64, per o and o+8 planes ----
    const int pw = (lane & 3) * 2;
    float* obase0 = out + ((((size_t)b * OC + og) * HH + h) * WW + w0 + pw);
    float* obase8 = obase0 + (size_t)8 * HH * WW;
#pragma unroll
    for (int g = 0; g < NGW; g++) {
        float2 v01; v01.x = d[g][0]; v01.y = d[g][1];
        float2 v23; v23.x = d[g][2]; v23.y = d[g][3];
        *(float2*)(obase0 + g * 8) = v01;
        *(float2*)(obase8 + g * 8) = v23;
    }
}

extern "C" void kernel_launch(void* const* d_in, const int* in_sizes, int n_in,
                              void* d_out, int out_size) {
    const float* x    = (const float*)d_in[0];
    const float* comb = (const float*)d_in[1];
    const float* bias = (const float*)d_in[2];
    float* out = (float*)d_out;

    dim3 grid(WW / WT, (HH + HT - 1) / HT, 4);   // (10, 57, 4)
    flow_mma_kernel<<<grid, 256>>>(x, comb, bias, out);
}

// round 3
// speedup vs baseline: 3.5171x; 1.2381x over previous
#include <cuda_runtime.h>
#include <cuda_fp16.h>
#include <cstdint>

// Flow_68015102099543 as implicit GEMM on tensor cores, single fp16 MMA, fp32 accum.
// out[b,o,h,w] = bias[o] + sum_{i,c} comb[o, i*16+c] * x[b,c,h+dy_i,w+dx_i]
// B=4, C=16, O=16, H=450, W=480. mma m16n8k16: A = weights (16o x 16c per flow),
// B = patches (16c x 8pix), D = 16o x 8pix fp32.

#define HH 450
#define WW 480
#define CH 16
#define OC 16

#define HT 8           // output rows per block (one per warp)
#define WT 48          // output cols per block
#define WS 50          // staged width  (WT + 2)
#define HS 10          // staged height (HT + 2)
#define NGW 6          // 8-pixel groups per row

__device__ __forceinline__ uint32_t smem_u32(const void* p) {
    return (uint32_t)__cvta_generic_to_shared(p);
}

__device__ __forceinline__ void ldsm_x4(uint32_t& r0, uint32_t& r1, uint32_t& r2, uint32_t& r3,
                                        uint32_t a) {
    asm volatile("ldmatrix.sync.aligned.m8n8.x4.shared.b16 {%0,%1,%2,%3}, [%4];"
                 : "=r"(r0), "=r"(r1), "=r"(r2), "=r"(r3) : "r"(a));
}
__device__ __forceinline__ void ldsm_x2(uint32_t& r0, uint32_t& r1, uint32_t a) {
    asm volatile("ldmatrix.sync.aligned.m8n8.x2.shared.b16 {%0,%1}, [%2];"
                 : "=r"(r0), "=r"(r1) : "r"(a));
}

__device__ __forceinline__ void mma_fp16(float& d0, float& d1, float& d2, float& d3,
                                         uint32_t a0, uint32_t a1, uint32_t a2, uint32_t a3,
                                         uint32_t b0, uint32_t b1) {
    asm volatile("mma.sync.aligned.m16n8k16.row.col.f32.f16.f16.f32 "
                 "{%0,%1,%2,%3}, {%4,%5,%6,%7}, {%8,%9}, {%0,%1,%2,%3};"
                 : "+f"(d0), "+f"(d1), "+f"(d2), "+f"(d3)
                 : "r"(a0), "r"(a1), "r"(a2), "r"(a3), "r"(b0), "r"(b1));
}

__global__ void __launch_bounds__(256) flow_mma_kernel(
    const float* __restrict__ x,      // [4,16,450,480]
    const float* __restrict__ comb,   // [16,144]
    const float* __restrict__ bias,   // [16]
    float* __restrict__ out)          // [4,16,450,480]
{
    // x tile: [h_s][w_s][half] units of 16B (8 fp16 channels), half swizzled by (w_s>>2)&1
    __shared__ uint4 xs4[HS * WS * 2];        // 16000 B
    // weights: [flow][o][half] units of 16B, half swizzled by (o>>2)&1
    __shared__ uint4 ws4[9 * OC * 2];         // 4608 B

    const int tid = threadIdx.x;
    const int b  = blockIdx.z;
    const int h0 = blockIdx.y * HT;
    const int w0 = blockIdx.x * WT;

    // ---- stage weights (fp32 -> fp16) ----
    for (int idx = tid; idx < 9 * OC * CH; idx += 256) {
        int i = idx >> 8;          // flow 0..8
        int o = (idx >> 4) & 15;
        int c = idx & 15;
        float v = comb[o * 144 + i * 16 + c];
        int half_ = c >> 3;
        int phys = (i * 16 + o) * 2 + (half_ ^ ((o >> 2) & 1));
        ((__half*)ws4)[phys * 8 + (c & 7)] = __float2half(v);
    }

    // ---- stage x tile: rows h0-1..h0+8, cols w0-1..w0+48, zero-padded ----
    for (int idx = tid; idx < HS * 2 * WS; idx += 256) {
        int w_s   = idx % WS;
        int t     = idx / WS;
        int half_ = t & 1;
        int h_s   = t >> 1;
        int gh = h0 - 1 + h_s;
        int gw = w0 - 1 + w_s;
        bool ok = ((unsigned)gh < (unsigned)HH) && ((unsigned)gw < (unsigned)WW);
        const float* xp = x + (((size_t)(b * CH + half_ * 8) * HH + gh) * WW + gw);
        float v[8];
#pragma unroll
        for (int cc = 0; cc < 8; cc++)
            v[cc] = ok ? __ldg(xp + (size_t)cc * (HH * WW)) : 0.0f;

        uint32_t u[4];
#pragma unroll
        for (int cc = 0; cc < 4; cc++) {
            __half2 p = __floats2half2_rn(v[2 * cc], v[2 * cc + 1]);  // .x = even c (low)
            u[cc] = *(uint32_t*)&p;
        }
        int phys = (h_s * WS + w_s) * 2 + (half_ ^ ((w_s >> 2) & 1));
        xs4[phys] = make_uint4(u[0], u[1], u[2], u[3]);
    }
    __syncthreads();

    const int warp = tid >> 5;
    const int lane = tid & 31;
    const int h = h0 + warp;
    if (h >= HH) return;   // whole-warp exit; no further barriers

    // D accumulators: d[g][0..1] = (o = lane>>2, pix = (lane&3)*2 + {0,1})
    //                 d[g][2..3] = (o+8, same pixels); init with bias.
    const int og = lane >> 2;
    const float b0v = __ldg(bias + og);
    const float b8v = __ldg(bias + 8 + og);
    float d[NGW][4];
#pragma unroll
    for (int g = 0; g < NGW; g++) { d[g][0] = b0v; d[g][1] = b0v; d[g][2] = b8v; d[g][3] = b8v; }

    const uint32_t wbase = smem_u32(ws4);
    const uint32_t xbase = smem_u32(xs4);

    // A fragment lane address (weights): 4 8x8 matrices in a0..a3 order
    const int o_l   = ((lane >> 3) & 1) * 8 + (lane & 7);
    const int ahalf = (lane >> 4) & 1;
    const uint32_t aoff = (uint32_t)((o_l * 2 + (ahalf ^ ((o_l >> 2) & 1))) * 16);

    // B fragment lane params: 2 8x8 matrices (pixels x c-halves)
    const int bp    = lane & 7;
    const int bhalf = (lane >> 3) & 1;

#pragma unroll
    for (int i = 0; i < 9; i++) {
        const int dy = i / 3, dx = i % 3;
        uint32_t a0, a1, a2, a3;
        ldsm_x4(a0, a1, a2, a3, wbase + (uint32_t)i * 512u + aoff);
        const int hrow = warp + dy;
#pragma unroll
        for (int g = 0; g < NGW; g++) {
            int w_s = dx + g * 8 + bp;
            uint32_t boff = (uint32_t)(((hrow * WS + w_s) * 2 + (bhalf ^ ((w_s >> 2) & 1))) * 16);
            uint32_t b0, b1;
            ldsm_x2(b0, b1, xbase + boff);
            mma_fp16(d[g][0], d[g][1], d[g][2], d[g][3], a0, a1, a2, a3, b0, b1);
        }
    }

    // ---- store: 2 consecutive pixels per STG.64, per o and o+8 planes ----
    const int pw = (lane & 3) * 2;
    float* obase0 = out + ((((size_t)b * OC + og) * HH + h) * WW + w0 + pw);
    float* obase8 = obase0 + (size_t)8 * HH * WW;
#pragma unroll
    for (int g = 0; g < NGW; g++) {
        float2 v01; v01.x = d[g][0]; v01.y = d[g][1];
        float2 v23; v23.x = d[g][2]; v23.y = d[g][3];
        *(float2*)(obase0 + g * 8) = v01;
        *(float2*)(obase8 + g * 8) = v23;
    }
}

extern "C" void kernel_launch(void* const* d_in, const int* in_sizes, int n_in,
                              void* d_out, int out_size) {
    const float* x    = (const float*)d_in[0];
    const float* comb = (const float*)d_in[1];
    const float* bias = (const float*)d_in[2];
    float* out = (float*)d_out;

    dim3 grid(WW / WT, (HH + HT - 1) / HT, 4);   // (10, 57, 4)
    flow_mma_kernel<<<grid, 256>>>(x, comb, bias, out);
}